// round 1
// baseline (speedup 1.0000x reference)
#include <cuda_runtime.h>
#include <math.h>

#define NEGC 1000000000000.0f

// Problem constants
// B=8, S=512, D=768, HEADS=16, HD=64, Ncols = HEADS*2*HD = 2048, Mrows = B*S = 4096
// logits: 8*16*512*512 = 33554432 floats, tri_mask: 8*512*512 = 2097152 floats

// Scratch: q,k stored as [b*16+h][d(64)][s(512)]  (transposed for conflict-free QK^T tiles)
__device__ float g_q[128 * 64 * 512];
__device__ float g_k[128 * 64 * 512];
__device__ float g_sin[512 * 32];
__device__ float g_cos[512 * 32];

// ---------------------------------------------------------------------------
// Kernel 0: RoPE sin/cos table. Double-precision trig so result is immune to
// -use_fast_math, while matching JAX's fp32 angle computation (angle formed in
// fp32: pos_f32 * invfreq_f32).
// ---------------------------------------------------------------------------
__global__ void rope_table_kernel() {
    int pos = blockIdx.x;      // 0..511
    int i   = threadIdx.x;     // 0..31  (pair index)
    double invd = pow(10000.0, -((double)(2 * i) / 64.0));
    float  angle = (float)pos * (float)invd;   // fp32 multiply, like jnp
    g_sin[pos * 32 + i] = (float)sin((double)angle);
    g_cos[pos * 32 + i] = (float)cos((double)angle);
}

// ---------------------------------------------------------------------------
// Kernel 1: C = hidden(4096x768) @ W(768x2048) + b, fused RoPE epilogue,
// writes q/k scratch in [bh][d][s] layout.
// Tiles: BM=128, BN=128, BK=16, 256 threads, 8x8 per thread.
// ---------------------------------------------------------------------------
__global__ __launch_bounds__(256) void proj_rope_kernel(
    const float* __restrict__ A,     // [4096][768]
    const float* __restrict__ Wm,    // [768][2048]
    const float* __restrict__ bias)  // [2048]
{
    __shared__ float As[16][128];   // [k][m] (transposed A tile)
    __shared__ float Bs[16][128];   // [k][n]

    const int tid = threadIdx.x;
    const int m0 = blockIdx.y * 128;
    const int n0 = blockIdx.x * 128;

    const int a_row = tid >> 2;           // 0..63
    const int a_col = (tid & 3) << 2;     // 0,4,8,12
    const int b_row = tid >> 5;           // 0..7
    const int b_col = (tid & 31) << 2;    // 0..124

    const int tm = (tid >> 4) << 3;       // row offset of this thread's 8 rows
    const int tn = (tid & 15) << 3;       // col offset of this thread's 8 cols

    float acc[8][8];
#pragma unroll
    for (int i = 0; i < 8; i++)
#pragma unroll
        for (int j = 0; j < 8; j++) acc[i][j] = 0.0f;

    for (int k0 = 0; k0 < 768; k0 += 16) {
        float4 av0 = *(const float4*)(A + (size_t)(m0 + a_row) * 768 + k0 + a_col);
        float4 av1 = *(const float4*)(A + (size_t)(m0 + a_row + 64) * 768 + k0 + a_col);
        float4 bv0 = *(const float4*)(Wm + (size_t)(k0 + b_row) * 2048 + n0 + b_col);
        float4 bv1 = *(const float4*)(Wm + (size_t)(k0 + b_row + 8) * 2048 + n0 + b_col);

        __syncthreads();
        As[a_col + 0][a_row] = av0.x;
        As[a_col + 1][a_row] = av0.y;
        As[a_col + 2][a_row] = av0.z;
        As[a_col + 3][a_row] = av0.w;
        As[a_col + 0][a_row + 64] = av1.x;
        As[a_col + 1][a_row + 64] = av1.y;
        As[a_col + 2][a_row + 64] = av1.z;
        As[a_col + 3][a_row + 64] = av1.w;
        *(float4*)&Bs[b_row][b_col]     = bv0;
        *(float4*)&Bs[b_row + 8][b_col] = bv1;
        __syncthreads();

#pragma unroll
        for (int k = 0; k < 16; k++) {
            float af[8], bf[8];
            *(float4*)&af[0] = *(float4*)&As[k][tm];
            *(float4*)&af[4] = *(float4*)&As[k][tm + 4];
            *(float4*)&bf[0] = *(float4*)&Bs[k][tn];
            *(float4*)&bf[4] = *(float4*)&Bs[k][tn + 4];
#pragma unroll
            for (int i = 0; i < 8; i++)
#pragma unroll
                for (int j = 0; j < 8; j++) acc[i][j] += af[i] * bf[j];
        }
    }

    // Epilogue: bias + RoPE + transposed scatter to g_q / g_k
    const int c0   = n0 + tn;          // 8 consecutive columns, aligned 8
    const int h    = c0 >> 7;          // head
    const int half = (c0 >> 6) & 1;    // 0 = q, 1 = k
    const int d0   = c0 & 63;          // head-dim base (multiple of 8)
    float* gbase = half ? g_k : g_q;

    float bj[8];
#pragma unroll
    for (int j = 0; j < 8; j++) bj[j] = bias[c0 + j];

#pragma unroll
    for (int i = 0; i < 8; i++) {
        int m = m0 + tm + i;
        int bidx = m >> 9;
        int s = m & 511;
        float* dst = gbase + ((size_t)(bidx * 16 + h) * 64) * 512 + s;
#pragma unroll
        for (int j = 0; j < 8; j += 2) {
            float x0 = acc[i][j] + bj[j];
            float x1 = acc[i][j + 1] + bj[j + 1];
            int pi = (d0 + j) >> 1;
            float sn = g_sin[s * 32 + pi];
            float cn = g_cos[s * 32 + pi];
            dst[(size_t)(d0 + j) * 512]     = x0 * cn - x1 * sn;
            dst[(size_t)(d0 + j + 1) * 512] = x1 * cn + x0 * sn;
        }
    }
}

// ---------------------------------------------------------------------------
// Kernel 2: logits + masks. One block = one 64x64 (m,n) tile of one (b,h).
// Tiles fully below the diagonal (m0 > n0) skip the dot product entirely:
// fl(raw - 1e12) == fl(0 - 1e12) exactly since |raw| << half-ulp(1e12).
// Mask subtractions are applied in the same order as the reference.
// ---------------------------------------------------------------------------
__global__ __launch_bounds__(256) void logits_kernel(
    const int* __restrict__ tok,
    float* __restrict__ out,
    float* __restrict__ out_tri,
    int write_tri)
{
    __shared__ float Qs[64][64];   // [d][m]
    __shared__ float Ks[64][64];   // [d][n]
    __shared__ float mqs[64];
    __shared__ float mks[64];

    const int tid = threadIdx.x;
    const int bh = blockIdx.z;
    const int b = bh >> 4;
    const int h = bh & 15;
    const int m0 = blockIdx.y << 6;
    const int n0 = blockIdx.x << 6;

    if (tid < 64) {
        mqs[tid] = (tok[b * 512 + m0 + tid] > 0) ? 1.0f : 0.0f;
    } else if (tid < 128) {
        mks[tid - 64] = (tok[b * 512 + n0 + (tid - 64)] > 0) ? 1.0f : 0.0f;
    }

    const bool compute = (m0 <= n0);   // uniform per block

    if (compute) {
        const float* qsrc = g_q + ((size_t)bh * 64) * 512;
        const float* ksrc = g_k + ((size_t)bh * 64) * 512;
        const int dl = tid >> 4;            // 0..15
        const int c4 = (tid & 15) << 2;     // 0..60
#pragma unroll
        for (int p = 0; p < 4; p++) {
            int d = dl + p * 16;
            *(float4*)&Qs[d][c4] = *(const float4*)(qsrc + (size_t)d * 512 + m0 + c4);
            *(float4*)&Ks[d][c4] = *(const float4*)(ksrc + (size_t)d * 512 + n0 + c4);
        }
    }
    __syncthreads();

    const int m4 = (tid >> 4) << 2;   // thread's 4 m rows
    const int n4 = (tid & 15) << 2;   // thread's 4 n cols (contiguous, write-coalesced)

    float acc[4][4];
#pragma unroll
    for (int i = 0; i < 4; i++)
#pragma unroll
        for (int j = 0; j < 4; j++) acc[i][j] = 0.0f;

    if (compute) {
#pragma unroll 16
        for (int d = 0; d < 64; d++) {
            float4 q = *(float4*)&Qs[d][m4];
            float4 k = *(float4*)&Ks[d][n4];
            float qa[4] = {q.x, q.y, q.z, q.w};
            float ka[4] = {k.x, k.y, k.z, k.w};
#pragma unroll
            for (int i = 0; i < 4; i++)
#pragma unroll
                for (int j = 0; j < 4; j++) acc[i][j] += qa[i] * ka[j];
        }
    }

    float* obase = out + ((size_t)bh << 18);   // bh * 512 * 512

#pragma unroll
    for (int i = 0; i < 4; i++) {
        int m = m0 + m4 + i;
        float mq = mqs[m4 + i];
#pragma unroll
        for (int j = 0; j < 4; j++) {
            int n = n0 + n4 + j;
            float mk = mks[n4 + j];
            float v = acc[i][j] * 0.125f;          // / sqrt(64)
            if (mq == 0.0f) v -= NEGC;             // query mask
            if (mk == 0.0f) v -= NEGC;             // key mask
            if (m > n)      v -= NEGC;             // strict lower triangle
            obase[(size_t)m * 512 + n] = v;
        }
        if (write_tri && h == 0) {
#pragma unroll
            for (int j = 0; j < 4; j++) {
                int n = n0 + n4 + j;
                float mk = mks[n4 + j];
                out_tri[((size_t)b * 512 + m) * 512 + n] = (m > n) ? 0.0f : mq * mk;
            }
        }
    }
}

// ---------------------------------------------------------------------------
extern "C" void kernel_launch(void* const* d_in, const int* in_sizes, int n_in,
                              void* d_out, int out_size) {
    // Map inputs by element count (robust to ordering):
    // hidden: 8*512*768 = 3145728, token_ids: 4096, W: 768*2048 = 1572864, b: 2048
    const float* hidden = nullptr;
    const int*   tok    = nullptr;
    const float* Wm     = nullptr;
    const float* bias   = nullptr;
    for (int i = 0; i < n_in; i++) {
        switch (in_sizes[i]) {
            case 3145728: hidden = (const float*)d_in[i]; break;
            case 4096:    tok    = (const int*)d_in[i];   break;
            case 1572864: Wm     = (const float*)d_in[i]; break;
            case 2048:    bias   = (const float*)d_in[i]; break;
            default: break;
        }
    }

    float* out = (float*)d_out;
    const long long logits_elems = 33554432LL;
    int write_tri = (out_size >= 35651584) ? 1 : 0;
    float* out_tri = out + logits_elems;

    rope_table_kernel<<<512, 32>>>();
    proj_rope_kernel<<<dim3(16, 32), 256>>>(hidden, Wm, bias);
    logits_kernel<<<dim3(8, 8, 128), 256>>>(tok, out, out_tri, write_tri);
}

// round 2
// speedup vs baseline: 4.2400x; 4.2400x over previous
#include <cuda_runtime.h>
#include <cuda_bf16.h>
#include <math.h>
#include <stdint.h>

#define NEGC 1000000000000.0f

// B=8, S=512, D=768, HEADS=16, HD=64, N=2048 cols, M=4096 rows
// logits: 33554432 floats, tri_mask: 2097152 floats

__device__ __align__(128) __nv_bfloat16 g_hid[4096 * 768];   // bf16 copy of hidden
__device__ __align__(128) __nv_bfloat16 g_Wt[2048 * 768];    // W transposed [n][k], bf16
__device__ __align__(128) __nv_bfloat16 g_q[128 * 512 * 64]; // [bh][s][d]
__device__ __align__(128) __nv_bfloat16 g_k[128 * 512 * 64];
__device__ float g_sin[512 * 32];
__device__ float g_cos[512 * 32];

// ---------------------------------------------------------------------------
// helpers
// ---------------------------------------------------------------------------
__device__ __forceinline__ uint32_t smem_u32(const void* p) {
    return (uint32_t)__cvta_generic_to_shared(p);
}
__device__ __forceinline__ void cp16(uint32_t dst, const void* src) {
    asm volatile("cp.async.cg.shared.global [%0], [%1], 16;\n" :: "r"(dst), "l"(src));
}
__device__ __forceinline__ void cp_commit() { asm volatile("cp.async.commit_group;\n"); }
template <int N> __device__ __forceinline__ void cp_wait() {
    asm volatile("cp.async.wait_group %0;\n" :: "n"(N));
}
// swizzled byte offset inside a tile of 128B rows; chunk = 16B unit 0..7
__device__ __forceinline__ uint32_t swz(int row, int chunk) {
    return (uint32_t)(row * 128 + ((chunk ^ (row & 7)) << 4));
}
__device__ __forceinline__ void ldm4(uint32_t addr, uint32_t& r0, uint32_t& r1,
                                     uint32_t& r2, uint32_t& r3) {
    asm volatile("ldmatrix.sync.aligned.m8n8.x4.shared.b16 {%0,%1,%2,%3}, [%4];\n"
                 : "=r"(r0), "=r"(r1), "=r"(r2), "=r"(r3) : "r"(addr));
}
__device__ __forceinline__ void mma_bf16(float* c, const uint32_t* a, const uint32_t* b) {
    asm volatile("mma.sync.aligned.m16n8k16.row.col.f32.bf16.bf16.f32 "
                 "{%0,%1,%2,%3},{%4,%5,%6,%7},{%8,%9},{%0,%1,%2,%3};\n"
                 : "+f"(c[0]), "+f"(c[1]), "+f"(c[2]), "+f"(c[3])
                 : "r"(a[0]), "r"(a[1]), "r"(a[2]), "r"(a[3]), "r"(b[0]), "r"(b[1]));
}

// ---------------------------------------------------------------------------
// Kernel: RoPE sin/cos table (fp32 trig; precision slack is enormous)
// ---------------------------------------------------------------------------
__global__ void rope_table_kernel() {
    int idx = blockIdx.x * blockDim.x + threadIdx.x;   // 16384
    int pos = idx >> 5, i = idx & 31;
    // inv_freq = 10000^(-2i/64)
    float inv = exp2f(-((float)(2 * i) / 64.0f) * 13.2877123795494f);
    float angle = (float)pos * inv;
    g_sin[idx] = sinf(angle);
    g_cos[idx] = cosf(angle);
}

// ---------------------------------------------------------------------------
// Kernel: hidden fp32 -> bf16
// ---------------------------------------------------------------------------
__global__ void conv_hid_kernel(const float* __restrict__ h) {
    int i = blockIdx.x * blockDim.x + threadIdx.x;     // handles 4 elems
    float4 v = ((const float4*)h)[i];
    __nv_bfloat162 lo, hi;
    lo.x = __float2bfloat16_rn(v.x); lo.y = __float2bfloat16_rn(v.y);
    hi.x = __float2bfloat16_rn(v.z); hi.y = __float2bfloat16_rn(v.w);
    ((__nv_bfloat162*)g_hid)[2 * i]     = lo;
    ((__nv_bfloat162*)g_hid)[2 * i + 1] = hi;
}

// ---------------------------------------------------------------------------
// Kernel: W [768][2048] fp32 -> Wt [2048][768] bf16 (smem transpose)
// ---------------------------------------------------------------------------
__global__ void conv_wt_kernel(const float* __restrict__ W) {
    __shared__ float tile[32][33];
    int nt = blockIdx.x * 32, kt = blockIdx.y * 32;
    int tx = threadIdx.x, ty = threadIdx.y;
#pragma unroll
    for (int j = 0; j < 4; j++)
        tile[ty + j * 8][tx] = W[(size_t)(kt + ty + j * 8) * 2048 + nt + tx];
    __syncthreads();
#pragma unroll
    for (int j = 0; j < 4; j++) {
        int n = nt + ty + j * 8;
        g_Wt[(size_t)n * 768 + kt + tx] = __float2bfloat16_rn(tile[tx][ty + j * 8]);
    }
}

// ---------------------------------------------------------------------------
// Kernel: projection GEMM (bf16 mma) + bias + RoPE epilogue -> g_q/g_k
// Block tile 128x128, BK=64, 8 warps (2M x 4N), warp tile 64x32.
// ---------------------------------------------------------------------------
__global__ __launch_bounds__(256) void proj_kernel(const float* __restrict__ bias) {
    extern __shared__ __align__(128) char smem[];
    const uint32_t sbase = smem_u32(smem);

    const int tid = threadIdx.x;
    const int lane = tid & 31;
    const int wid = tid >> 5;
    const int wm = (wid >> 2) * 64;    // warp m offset (0,64)
    const int wn = (wid & 3) * 32;     // warp n offset (0,32,64,96)
    const int m0 = blockIdx.y * 128;
    const int n0 = blockIdx.x * 128;

    float acc[4][4][4];
#pragma unroll
    for (int i = 0; i < 4; i++)
#pragma unroll
        for (int j = 0; j < 4; j++)
#pragma unroll
            for (int r = 0; r < 4; r++) acc[i][j][r] = 0.0f;

    // stage layout: [stage][A 16KB | B 16KB]
    auto load_stage = [&](int stage, int k0) {
        const __nv_bfloat16* Ag = g_hid + (size_t)m0 * 768 + k0;
        const __nv_bfloat16* Bg = g_Wt + (size_t)n0 * 768 + k0;
        uint32_t sA = sbase + stage * 32768;
        uint32_t sB = sA + 16384;
#pragma unroll
        for (int i = 0; i < 4; i++) {
            int idx = i * 256 + tid;
            int row = idx >> 3, ch = idx & 7;
            cp16(sA + swz(row, ch), Ag + (size_t)row * 768 + ch * 8);
            cp16(sB + swz(row, ch), Bg + (size_t)row * 768 + ch * 8);
        }
    };

    auto compute_stage = [&](int stage) {
        uint32_t sA = sbase + stage * 32768;
        uint32_t sB = sA + 16384;
#pragma unroll
        for (int ks = 0; ks < 4; ks++) {
            uint32_t a[4][4];
#pragma unroll
            for (int mi = 0; mi < 4; mi++) {
                int row = wm + mi * 16 + (lane & 15);
                int ch = ks * 2 + (lane >> 4);
                ldm4(sA + swz(row, ch), a[mi][0], a[mi][1], a[mi][2], a[mi][3]);
            }
            uint32_t b[4][2];
#pragma unroll
            for (int nb = 0; nb < 2; nb++) {
                int row = wn + nb * 16 + (lane & 7) + ((lane >> 4) << 3);
                int ch = ks * 2 + ((lane >> 3) & 1);
                uint32_t r0, r1, r2, r3;
                ldm4(sB + swz(row, ch), r0, r1, r2, r3);
                b[nb * 2][0] = r0;     b[nb * 2][1] = r1;
                b[nb * 2 + 1][0] = r2; b[nb * 2 + 1][1] = r3;
            }
#pragma unroll
            for (int mi = 0; mi < 4; mi++)
#pragma unroll
                for (int nj = 0; nj < 4; nj++)
                    mma_bf16(acc[mi][nj], a[mi], b[nj]);
        }
    };

    load_stage(0, 0);
    cp_commit();
    for (int it = 0; it < 12; it++) {
        if (it + 1 < 12) {
            load_stage((it + 1) & 1, (it + 1) * 64);
            cp_commit();
            cp_wait<1>();
        } else {
            cp_wait<0>();
        }
        __syncthreads();
        compute_stage(it & 1);
        __syncthreads();
    }

    // Epilogue: bias + RoPE, write bf16 pairs to g_q / g_k in [bh][s][d]
    const int r0l = lane >> 2;
    const int c2l = (lane & 3) * 2;
#pragma unroll
    for (int nj = 0; nj < 4; nj++) {
        int ncol = n0 + wn + nj * 8 + c2l;        // even
        int h = ncol >> 7;
        int half = (ncol >> 6) & 1;
        int d0 = ncol & 63;                        // even
        int pi = d0 >> 1;
        float b0v = bias[ncol], b1v = bias[ncol + 1];
        __nv_bfloat16* gb = half ? g_k : g_q;
#pragma unroll
        for (int mi = 0; mi < 4; mi++) {
#pragma unroll
            for (int rr = 0; rr < 2; rr++) {
                int m = m0 + wm + mi * 16 + r0l + rr * 8;
                int bi = m >> 9, s = m & 511;
                float x0 = acc[mi][nj][rr * 2 + 0] + b0v;
                float x1 = acc[mi][nj][rr * 2 + 1] + b1v;
                float sn = g_sin[s * 32 + pi];
                float cn = g_cos[s * 32 + pi];
                __nv_bfloat162 v;
                v.x = __float2bfloat16_rn(x0 * cn - x1 * sn);
                v.y = __float2bfloat16_rn(x1 * cn + x0 * sn);
                *(__nv_bfloat162*)(gb + ((size_t)((bi * 16 + h) * 512 + s)) * 64 + d0) = v;
            }
        }
    }
}

// ---------------------------------------------------------------------------
// Kernel: logits = (Q K^T)/8 with masks. Block = 128x128 tile of one (b,h).
// Fully-below-diagonal tiles skip the mma (bit-equivalent: fl(x-1e12) = -1e12
// for |x| << half-ulp(1e12)).
// ---------------------------------------------------------------------------
__global__ __launch_bounds__(256) void logits_kernel(
    const int* __restrict__ tok, float* __restrict__ out)
{
    __shared__ __align__(128) __nv_bfloat16 smQ[128 * 64];
    __shared__ __align__(128) __nv_bfloat16 smK[128 * 64];
    __shared__ float mqs[128];
    __shared__ float mks[128];

    const int tid = threadIdx.x;
    const int lane = tid & 31;
    const int wid = tid >> 5;
    const int wm = (wid >> 2) * 64;
    const int wn = (wid & 3) * 32;
    const int bh = blockIdx.z;
    const int b = bh >> 4;
    const int m0 = blockIdx.y << 7;
    const int n0 = blockIdx.x << 7;

    if (tid < 128) mqs[tid] = (tok[b * 512 + m0 + tid] > 0) ? 1.0f : 0.0f;
    else           mks[tid - 128] = (tok[b * 512 + n0 + tid - 128] > 0) ? 1.0f : 0.0f;

    const bool compute = (m0 <= n0);   // uniform per block
    const uint32_t sQ = smem_u32(smQ);
    const uint32_t sK = smem_u32(smK);

    if (compute) {
        const __nv_bfloat16* Qg = g_q + (size_t)(bh * 512 + m0) * 64;
        const __nv_bfloat16* Kg = g_k + (size_t)(bh * 512 + n0) * 64;
#pragma unroll
        for (int i = 0; i < 4; i++) {
            int idx = i * 256 + tid;
            int row = idx >> 3, ch = idx & 7;
            cp16(sQ + swz(row, ch), Qg + (size_t)row * 64 + ch * 8);
            cp16(sK + swz(row, ch), Kg + (size_t)row * 64 + ch * 8);
        }
        cp_commit();
    }
    cp_wait<0>();
    __syncthreads();

    float acc[4][4][4];
#pragma unroll
    for (int i = 0; i < 4; i++)
#pragma unroll
        for (int j = 0; j < 4; j++)
#pragma unroll
            for (int r = 0; r < 4; r++) acc[i][j][r] = 0.0f;

    if (compute) {
#pragma unroll
        for (int ks = 0; ks < 4; ks++) {
            uint32_t a[4][4];
#pragma unroll
            for (int mi = 0; mi < 4; mi++) {
                int row = wm + mi * 16 + (lane & 15);
                int ch = ks * 2 + (lane >> 4);
                ldm4(sQ + swz(row, ch), a[mi][0], a[mi][1], a[mi][2], a[mi][3]);
            }
            uint32_t bfr[4][2];
#pragma unroll
            for (int nb = 0; nb < 2; nb++) {
                int row = wn + nb * 16 + (lane & 7) + ((lane >> 4) << 3);
                int ch = ks * 2 + ((lane >> 3) & 1);
                uint32_t r0, r1, r2, r3;
                ldm4(sK + swz(row, ch), r0, r1, r2, r3);
                bfr[nb * 2][0] = r0;     bfr[nb * 2][1] = r1;
                bfr[nb * 2 + 1][0] = r2; bfr[nb * 2 + 1][1] = r3;
            }
#pragma unroll
            for (int mi = 0; mi < 4; mi++)
#pragma unroll
                for (int nj = 0; nj < 4; nj++)
                    mma_bf16(acc[mi][nj], a[mi], bfr[nj]);
        }
    }

    float* obase = out + ((size_t)bh << 18);
    const int r0l = lane >> 2;
    const int c2l = (lane & 3) * 2;
#pragma unroll
    for (int mi = 0; mi < 4; mi++) {
#pragma unroll
        for (int rr = 0; rr < 2; rr++) {
            int m = m0 + wm + mi * 16 + r0l + rr * 8;
            float mq = mqs[m - m0];
#pragma unroll
            for (int nj = 0; nj < 4; nj++) {
                int n = n0 + wn + nj * 8 + c2l;
                float mk0 = mks[n - n0], mk1 = mks[n - n0 + 1];
                float v0 = acc[mi][nj][rr * 2 + 0] * 0.125f;
                float v1 = acc[mi][nj][rr * 2 + 1] * 0.125f;
                if (mq == 0.0f)  { v0 -= NEGC; v1 -= NEGC; }
                if (mk0 == 0.0f)   v0 -= NEGC;
                if (mk1 == 0.0f)   v1 -= NEGC;
                if (m > n)         v0 -= NEGC;
                if (m > n + 1)     v1 -= NEGC;
                float2 o; o.x = v0; o.y = v1;
                *(float2*)(obase + (size_t)m * 512 + n) = o;
            }
        }
    }
}

// ---------------------------------------------------------------------------
// Kernel: tri_mask[b][m][n] = (m>n) ? 0 : mq*mk
// ---------------------------------------------------------------------------
__global__ void tri_kernel(const int* __restrict__ tok, float* __restrict__ out_tri) {
    int row = blockIdx.x;            // b*512 + m
    int b = row >> 9, m = row & 511;
    float mq = (tok[row] > 0) ? 1.0f : 0.0f;
    int t = threadIdx.x;             // 128
    int n = t * 4;
    float4 v;
    float* vv = (float*)&v;
#pragma unroll
    for (int j = 0; j < 4; j++) {
        int nn = n + j;
        float mk = (tok[b * 512 + nn] > 0) ? 1.0f : 0.0f;
        vv[j] = (m > nn) ? 0.0f : mq * mk;
    }
    ((float4*)(out_tri + (size_t)row * 512))[t] = v;
}

// ---------------------------------------------------------------------------
extern "C" void kernel_launch(void* const* d_in, const int* in_sizes, int n_in,
                              void* d_out, int out_size) {
    const float* hidden = nullptr;
    const int*   tok    = nullptr;
    const float* Wm     = nullptr;
    const float* bias   = nullptr;
    for (int i = 0; i < n_in; i++) {
        switch (in_sizes[i]) {
            case 3145728: hidden = (const float*)d_in[i]; break;
            case 4096:    tok    = (const int*)d_in[i];   break;
            case 1572864: Wm     = (const float*)d_in[i]; break;
            case 2048:    bias   = (const float*)d_in[i]; break;
            default: break;
        }
    }

    float* out = (float*)d_out;
    const long long logits_elems = 33554432LL;
    int write_tri = (out_size >= 35651584) ? 1 : 0;
    float* out_tri = out + logits_elems;

    static int smem_set = 0;
    if (!smem_set) {
        cudaFuncSetAttribute(proj_kernel, cudaFuncAttributeMaxDynamicSharedMemorySize, 65536);
        smem_set = 1;
    }

    rope_table_kernel<<<32, 512>>>();
    conv_hid_kernel<<<3072, 256>>>(hidden);
    conv_wt_kernel<<<dim3(64, 24), dim3(32, 8)>>>(Wm);
    proj_kernel<<<dim3(16, 32), 256, 65536>>>(bias);
    logits_kernel<<<dim3(4, 4, 128), 256>>>(tok, out);
    if (write_tri) tri_kernel<<<4096, 128>>>(tok, out_tri);
}